// round 13
// baseline (speedup 1.0000x reference)
#include <cuda_runtime.h>
#include <cuda_bf16.h>
#include <math.h>
#include <stdint.h>

#define BB   8
#define LL   1024
#define DD   1024
#define DFF  4096
#define MDD  6
#define ROWS (BB * LL)
#define NCUR (ROWS * DD)

typedef __nv_bfloat16 bf16;

// ---------------- device scratch ----------------
__device__ float g_cur[NCUR];          // permuted token order
__device__ float g_x2[NCUR];
__device__ float g_rh[NCUR];
__device__ float g_logits[ROWS * MDD];
__device__ int   g_depths[ROWS];
__device__ int   g_dsort[ROWS];
__device__ int   g_perm[ROWS];
__device__ int   g_inv[ROWS];

__device__ bf16 g_lnh[NCUR],  g_lnl[NCUR];
__device__ bf16 g_qkvh[ROWS * 3 * DD], g_qkvl[ROWS * 3 * DD];
__device__ bf16 g_vTh[(size_t)128 * 64 * LL], g_vTl[(size_t)128 * 64 * LL];
__device__ bf16 g_ctxh[NCUR], g_ctxl[NCUR];
__device__ bf16 g_hidh[(size_t)ROWS * DFF], g_hidl[(size_t)ROWS * DFF];
__device__ bf16 g_wqh[3 * DD * DD], g_wql[3 * DD * DD];
__device__ bf16 g_woh[DD * DD],     g_wol[DD * DD];
__device__ bf16 g_w1h[DFF * DD],    g_w1l[DFF * DD];
__device__ bf16 g_w2h[DD * DFF],    g_w2l[DD * DFF];
__device__ bf16 g_rwh[DD * DD],     g_rwl[DD * DD];

// ---------------- helpers ----------------
__device__ __forceinline__ uint32_t smem_u32(const void* p) {
    uint32_t a;
    asm("{ .reg .u64 t; cvta.to.shared.u64 t, %1; cvt.u32.u64 %0, t; }" : "=r"(a) : "l"(p));
    return a;
}
__device__ __forceinline__ void cp16(uint32_t dst, const void* src) {
    asm volatile("cp.async.cg.shared.global [%0], [%1], 16;" :: "r"(dst), "l"(src));
}
__device__ __forceinline__ void ldmx4(uint32_t addr, uint32_t* r) {
    asm volatile("ldmatrix.sync.aligned.m8n8.x4.shared.b16 {%0,%1,%2,%3}, [%4];"
        : "=r"(r[0]), "=r"(r[1]), "=r"(r[2]), "=r"(r[3]) : "r"(addr));
}
__device__ __forceinline__ void mma_bf16(float* c, const uint32_t* a, const uint32_t* b) {
    asm volatile("mma.sync.aligned.m16n8k16.row.col.f32.bf16.bf16.f32 "
        "{%0,%1,%2,%3}, {%4,%5,%6,%7}, {%8,%9}, {%0,%1,%2,%3};"
        : "+f"(c[0]), "+f"(c[1]), "+f"(c[2]), "+f"(c[3])
        : "r"(a[0]), "r"(a[1]), "r"(a[2]), "r"(a[3]), "r"(b[0]), "r"(b[1]));
}
__device__ __forceinline__ void split_pair(float v, bf16& h, bf16& l) {
    h = __float2bfloat16_rn(v);
    l = __float2bfloat16_rn(v - __bfloat162float(h));
}
__device__ __forceinline__ uint32_t pack_hl(float x, float y, uint32_t& lo) {
    __nv_bfloat162 hv = __floats2bfloat162_rn(x, y);
    float2 f = __bfloat1622float2(hv);
    __nv_bfloat162 lv = __floats2bfloat162_rn(x - f.x, y - f.y);
    lo = *(uint32_t*)&lv;
    return *(uint32_t*)&hv;
}
__device__ __forceinline__ float gelu_erf(float x) {
    return 0.5f * x * (1.0f + erff(x * 0.70710678118654752440f));
}
__device__ __forceinline__ float warp_sum(float v) {
    #pragma unroll
    for (int o = 16; o > 0; o >>= 1) v += __shfl_xor_sync(0xffffffffu, v, o);
    return v;
}
__device__ __forceinline__ float warp_max(float v) {
    #pragma unroll
    for (int o = 16; o > 0; o >>= 1) v = fmaxf(v, __shfl_xor_sync(0xffffffffu, v, o));
    return v;
}

// ---------------------------------------------------------------------------
// Dense split-bf16 NT GEMM — Round-10/12 validated fragment math; loop now
// uses ONE __syncthreads per chunk (ISSUE of the overwriting stage moved
// after the barrier that retires its previous readers).
// ---------------------------------------------------------------------------
template<int MT>
__device__ __forceinline__ void compute_chunk64(uint32_t stg, uint32_t wloffB,
                                                int warp_m, int warp_n,
                                                int lane, float* acc)
{
    const uint32_t aA = stg + (warp_m * (MT * 16) + (lane & 15)) * 80 + ((lane >> 4) & 1) * 16;
    const uint32_t aB = stg + 20480
        + (warp_n * 64 + (lane & 7) + ((lane >> 4) & 1) * 8) * 80 + ((lane >> 3) & 1) * 16;
    #pragma unroll
    for (int ks = 0; ks < 2; ks++) {
        const uint32_t kso = ks * 32;
        uint32_t bh[8][2], bl[8][2];
        #pragma unroll
        for (int ntp = 0; ntp < 4; ntp++) {
            uint32_t t4[4];
            ldmx4(aB + ntp * 1280 + kso, t4);
            bh[2 * ntp][0] = t4[0]; bh[2 * ntp][1] = t4[1];
            bh[2 * ntp + 1][0] = t4[2]; bh[2 * ntp + 1][1] = t4[3];
            ldmx4(aB + wloffB + ntp * 1280 + kso, t4);
            bl[2 * ntp][0] = t4[0]; bl[2 * ntp][1] = t4[1];
            bl[2 * ntp + 1][0] = t4[2]; bl[2 * ntp + 1][1] = t4[3];
        }
        #pragma unroll
        for (int mt = 0; mt < MT; mt++) {
            uint32_t ah[4], al[4];
            ldmx4(aA + mt * 1280 + kso, ah);
            ldmx4(aA + 10240 + mt * 1280 + kso, al);
            #pragma unroll
            for (int nt = 0; nt < 8; nt++) {
                float* c = acc + (mt * 8 + nt) * 4;
                mma_bf16(c, ah, bh[nt]);
                mma_bf16(c, ah, bl[nt]);
                mma_bf16(c, al, bh[nt]);
            }
        }
    }
}

template<int EPI, int NTILE, int OUTP, int DSKIP, int QSPLIT>
__global__ void __launch_bounds__(128)
gemm_bf(const bf16* __restrict__ Ah, const bf16* __restrict__ Al, int lda, long saz, long sah,
        const bf16* __restrict__ Wh, const bf16* __restrict__ Wl, int ldw, long swz, long swh,
        const float* __restrict__ bias, const float* __restrict__ res,
        const int* __restrict__ depths, int level, long sdz,
        float* __restrict__ Cf, bf16* __restrict__ Ch, bf16* __restrict__ Cl,
        int ldc, long scz, long sch, int hsh, int hmk, int K)
{
    extern __shared__ __align__(16) char smem[];
    constexpr int WN  = NTILE / 64;
    constexpr int MT  = (WN == 2) ? 4 : 2;
    constexpr int STG = 20480 + NTILE * 160;
    const int tid = threadIdx.x, lane = tid & 31, wid = tid >> 5;
    const int warp_m = wid / WN, warp_n = wid % WN;
    const int z = blockIdx.z, zh = z >> hsh, zl = z & hmk;
    const int m0 = blockIdx.y << 7, n0 = blockIdx.x * NTILE;
    if (DSKIP) {
        int thr = (QSPLIT && n0 >= DD) ? level - 1 : level;
        if (depths[(size_t)zh * sdz + m0] < thr) return;
    }
    const size_t aoff = (size_t)zh * saz + (size_t)zl * sah + (size_t)m0 * lda;
    const size_t woff = (size_t)zh * swz + (size_t)zl * swh + (size_t)n0 * ldw;
    const bf16* Azh = Ah + aoff;
    const bf16* Azl = Al + aoff;
    const bf16* Wzh = Wh + woff;
    const bf16* Wzl = Wl + woff;
    const uint32_t sb = smem_u32(smem);

    float acc[MT * 8 * 4];
    #pragma unroll
    for (int i = 0; i < MT * 8 * 4; i++) acc[i] = 0.0f;

    const int rr0 = tid >> 2, gg = tid & 3;
    const int nchunk = K >> 5;

    #define ISSUE(cc) do { \
        uint32_t st = sb + ((cc) & 1) * STG; \
        const size_t ko = (size_t)((cc) << 5); \
        _Pragma("unroll") \
        for (int i = 0; i < 4; i++) { \
            int r = rr0 + i * 32; \
            cp16(st + r * 80 + gg * 16,         Azh + (size_t)r * lda + ko + gg * 8); \
            cp16(st + 10240 + r * 80 + gg * 16, Azl + (size_t)r * lda + ko + gg * 8); \
        } \
        _Pragma("unroll") \
        for (int i = 0; i < NTILE / 32; i++) { \
            int r = rr0 + i * 32; \
            cp16(st + 20480 + r * 80 + gg * 16,              Wzh + (size_t)r * ldw + ko + gg * 8); \
            cp16(st + 20480 + NTILE * 80 + r * 80 + gg * 16, Wzl + (size_t)r * ldw + ko + gg * 8); \
        } \
        asm volatile("cp.async.commit_group;" ::: "memory"); \
    } while (0)

    ISSUE(0);
    for (int c = 0; c < nchunk; c++) {
        asm volatile("cp.async.wait_group 0;" ::: "memory");
        __syncthreads();                     // chunk c visible; c-1 readers retired
        if (c + 1 < nchunk) ISSUE(c + 1);    // overwrites stage (c-1)&1 — safe
        compute_chunk64<MT>(sb + (c & 1) * STG, (uint32_t)(NTILE * 80),
                            warp_m, warp_n, lane, acc);
    }
    #undef ISSUE

    const size_t coff = (size_t)zh * scz + (size_t)zl * sch;
    #pragma unroll
    for (int mt = 0; mt < MT; mt++) {
        #pragma unroll
        for (int h2 = 0; h2 < 2; h2++) {
            const int m = m0 + warp_m * (MT * 16) + mt * 16 + (lane >> 2) + h2 * 8;
            if (EPI == 4) { if (depths[m] < level) continue; }
            const float* Rrow = (EPI >= 3) ? (res + (size_t)m * ldc) : (const float*)0;
            #pragma unroll
            for (int nt = 0; nt < 8; nt++) {
                const int col = n0 + warp_n * 64 + nt * 8 + ((lane & 3) << 1);
                float vx = acc[(mt * 8 + nt) * 4 + h2 * 2 + 0];
                float vy = acc[(mt * 8 + nt) * 4 + h2 * 2 + 1];
                if (EPI >= 1) { vx += bias[col]; vy += bias[col + 1]; }
                if (EPI == 2) { vx = gelu_erf(vx); vy = gelu_erf(vy); }
                if (EPI >= 3) { vx += Rrow[col]; vy += Rrow[col + 1]; }
                if (OUTP == 0) {
                    *(float2*)(Cf + coff + (size_t)m * ldc + col) = make_float2(vx, vy);
                } else {
                    uint32_t lo, hi = pack_hl(vx, vy, lo);
                    *(uint32_t*)(Ch + coff + (size_t)m * ldc + col) = hi;
                    *(uint32_t*)(Cl + coff + (size_t)m * ldc + col) = lo;
                }
            }
        }
    }
}

// ---------------------------------------------------------------------------
// Flash-fused attention: single barrier per KV block; B/V fragments via the
// ldmx4 pair-trick (same bytes/fragments as the validated ldmx2 version).
// smem: Q hi/lo @0 (18432) | K stages @18432 (2x18432) | vT stages @55296.
// ---------------------------------------------------------------------------
__global__ void __launch_bounds__(128)
flash_kernel(const bf16* __restrict__ qkvh, const bf16* __restrict__ qkvl,
             const bf16* __restrict__ vTh, const bf16* __restrict__ vTl,
             bf16* __restrict__ ctxh, bf16* __restrict__ ctxl,
             const int* __restrict__ dsort, int level)
{
    extern __shared__ __align__(16) char smem[];
    const int z = blockIdx.y, b = z >> 4, h = z & 15;
    const int qb = blockIdx.x;
    if (dsort[b * 1024 + qb * 64] < level) return;
    const int tid = threadIdx.x, lane = tid & 31, wq = tid >> 5;
    const uint32_t sb = smem_u32(smem);

    const size_t qbase = ((size_t)b * 1024 + (size_t)qb * 64) * 3072 + h * 64;
    const size_t kbase = (size_t)b * 1024 * 3072 + 1024 + h * 64;
    const size_t vbase = (size_t)z * 65536;

    #pragma unroll
    for (int i = 0; i < 4; i++) {
        int idx = tid + i * 128, row = idx >> 3, g = idx & 7;
        cp16(sb + row * 144 + g * 16,        qkvh + qbase + (size_t)row * 3072 + g * 8);
        cp16(sb + 9216 + row * 144 + g * 16, qkvl + qbase + (size_t)row * 3072 + g * 8);
    }
    asm volatile("cp.async.commit_group;" ::: "memory");

    #define KV_ISSUE(kb) do { \
        uint32_t st = ((kb) & 1) * 18432; \
        _Pragma("unroll") \
        for (int i = 0; i < 4; i++) { \
            int idx = tid + i * 128, row = idx >> 3, g = idx & 7; \
            size_t ks = kbase + ((size_t)((kb) * 64 + row)) * 3072 + g * 8; \
            cp16(sb + 18432 + st + row * 144 + g * 16,        qkvh + ks); \
            cp16(sb + 18432 + st + 9216 + row * 144 + g * 16, qkvl + ks); \
            size_t vs = vbase + (size_t)row * 1024 + (kb) * 64 + g * 8; \
            cp16(sb + 55296 + st + row * 144 + g * 16,        vTh + vs); \
            cp16(sb + 55296 + st + 9216 + row * 144 + g * 16, vTl + vs); \
        } \
        asm volatile("cp.async.commit_group;" ::: "memory"); \
    } while (0)

    KV_ISSUE(0);

    uint32_t qh_[4][4], ql_[4][4];
    float oacc[8][4];
    #pragma unroll
    for (int nt = 0; nt < 8; nt++)
        #pragma unroll
        for (int j = 0; j < 4; j++) oacc[nt][j] = 0.0f;
    float m0 = -1e30f, m1 = -1e30f, l0 = 0.0f, l1 = 0.0f;

    const uint32_t qa = sb + (wq * 16 + (lane & 15)) * 144 + ((lane >> 4) & 1) * 16;
    // pair-trick B addressing: lanes 16-31 take rows +8 (next nt of the pair)
    const uint32_t bofs = ((lane & 7) + ((lane >> 4) & 1) * 8) * 144 + ((lane >> 3) & 1) * 16;

    for (int kb = 0; kb < 16; kb++) {
        asm volatile("cp.async.wait_group 0;" ::: "memory");
        __syncthreads();                          // KV(kb) visible; kb-1 readers done
        if (kb + 1 < 16) KV_ISSUE(kb + 1);        // overwrites stage (kb-1)&1 — safe
        if (kb == 0) {
            #pragma unroll
            for (int kc = 0; kc < 4; kc++) {
                ldmx4(qa + kc * 32, qh_[kc]);
                ldmx4(qa + 9216 + kc * 32, ql_[kc]);
            }
        }
        // ---- S = Q @ K^T ----
        const uint32_t kt = sb + 18432 + (kb & 1) * 18432 + bofs;
        float s[8][4];
        #pragma unroll
        for (int nt = 0; nt < 8; nt++)
            #pragma unroll
            for (int j = 0; j < 4; j++) s[nt][j] = 0.0f;
        #pragma unroll
        for (int kc = 0; kc < 4; kc++) {
            uint32_t bh[8][2], bl[8][2];
            #pragma unroll
            for (int ntp = 0; ntp < 4; ntp++) {
                uint32_t t4[4];
                ldmx4(kt + ntp * 2304 + kc * 32, t4);
                bh[2 * ntp][0] = t4[0]; bh[2 * ntp][1] = t4[1];
                bh[2 * ntp + 1][0] = t4[2]; bh[2 * ntp + 1][1] = t4[3];
                ldmx4(kt + 9216 + ntp * 2304 + kc * 32, t4);
                bl[2 * ntp][0] = t4[0]; bl[2 * ntp][1] = t4[1];
                bl[2 * ntp + 1][0] = t4[2]; bl[2 * ntp + 1][1] = t4[3];
            }
            #pragma unroll
            for (int nt = 0; nt < 8; nt++) {
                mma_bf16(s[nt], qh_[kc], bh[nt]);
                mma_bf16(s[nt], qh_[kc], bl[nt]);
                mma_bf16(s[nt], ql_[kc], bh[nt]);
            }
        }
        // ---- online softmax (scale 1/8) ----
        float mx0 = -1e30f, mx1 = -1e30f;
        #pragma unroll
        for (int nt = 0; nt < 8; nt++) {
            mx0 = fmaxf(mx0, fmaxf(s[nt][0], s[nt][1]));
            mx1 = fmaxf(mx1, fmaxf(s[nt][2], s[nt][3]));
        }
        mx0 = fmaxf(mx0, __shfl_xor_sync(0xffffffffu, mx0, 1));
        mx0 = fmaxf(mx0, __shfl_xor_sync(0xffffffffu, mx0, 2));
        mx1 = fmaxf(mx1, __shfl_xor_sync(0xffffffffu, mx1, 1));
        mx1 = fmaxf(mx1, __shfl_xor_sync(0xffffffffu, mx1, 2));
        const float nm0 = fmaxf(m0, mx0 * 0.125f);
        const float nm1 = fmaxf(m1, mx1 * 0.125f);
        const float a0 = __expf(m0 - nm0);
        const float a1 = __expf(m1 - nm1);
        float rs0 = 0.0f, rs1 = 0.0f;
        #pragma unroll
        for (int nt = 0; nt < 8; nt++) {
            s[nt][0] = __expf(s[nt][0] * 0.125f - nm0);
            s[nt][1] = __expf(s[nt][1] * 0.125f - nm0);
            s[nt][2] = __expf(s[nt][2] * 0.125f - nm1);
            s[nt][3] = __expf(s[nt][3] * 0.125f - nm1);
            rs0 += s[nt][0] + s[nt][1];
            rs1 += s[nt][2] + s[nt][3];
        }
        rs0 += __shfl_xor_sync(0xffffffffu, rs0, 1);
        rs0 += __shfl_xor_sync(0xffffffffu, rs0, 2);
        rs1 += __shfl_xor_sync(0xffffffffu, rs1, 1);
        rs1 += __shfl_xor_sync(0xffffffffu, rs1, 2);
        l0 = a0 * l0 + rs0;
        l1 = a1 * l1 + rs1;
        m0 = nm0; m1 = nm1;
        #pragma unroll
        for (int nt = 0; nt < 8; nt++) {
            oacc[nt][0] *= a0; oacc[nt][1] *= a0;
            oacc[nt][2] *= a1; oacc[nt][3] *= a1;
        }
        // ---- ctx += P @ V ----
        const uint32_t vt = sb + 55296 + (kb & 1) * 18432 + bofs;
        #pragma unroll
        for (int kc = 0; kc < 4; kc++) {
            uint32_t pah[4], pal[4];
            pah[0] = pack_hl(s[2 * kc][0],     s[2 * kc][1],     pal[0]);
            pah[1] = pack_hl(s[2 * kc][2],     s[2 * kc][3],     pal[1]);
            pah[2] = pack_hl(s[2 * kc + 1][0], s[2 * kc + 1][1], pal[2]);
            pah[3] = pack_hl(s[2 * kc + 1][2], s[2 * kc + 1][3], pal[3]);
            uint32_t vbh[8][2], vbl[8][2];
            #pragma unroll
            for (int ntp = 0; ntp < 4; ntp++) {
                uint32_t t4[4];
                ldmx4(vt + ntp * 2304 + kc * 32, t4);
                vbh[2 * ntp][0] = t4[0]; vbh[2 * ntp][1] = t4[1];
                vbh[2 * ntp + 1][0] = t4[2]; vbh[2 * ntp + 1][1] = t4[3];
                ldmx4(vt + 9216 + ntp * 2304 + kc * 32, t4);
                vbl[2 * ntp][0] = t4[0]; vbl[2 * ntp][1] = t4[1];
                vbl[2 * ntp + 1][0] = t4[2]; vbl[2 * ntp + 1][1] = t4[3];
            }
            #pragma unroll
            for (int nt = 0; nt < 8; nt++) {
                mma_bf16(oacc[nt], pah, vbh[nt]);
                mma_bf16(oacc[nt], pah, vbl[nt]);
                mma_bf16(oacc[nt], pal, vbh[nt]);
            }
        }
    }
    #undef KV_ISSUE

    const float i0 = 1.0f / l0, i1 = 1.0f / l1;
    const int token = b * 1024 + qb * 64 + wq * 16 + (lane >> 2);
    const size_t ob  = (size_t)token * 1024 + h * 64;
    const size_t ob8 = ob + 8 * 1024;
    #pragma unroll
    for (int nt = 0; nt < 8; nt++) {
        const int d = nt * 8 + ((lane & 3) << 1);
        uint32_t lo, hi;
        hi = pack_hl(oacc[nt][0] * i0, oacc[nt][1] * i0, lo);
        *(uint32_t*)(ctxh + ob + d) = hi;
        *(uint32_t*)(ctxl + ob + d) = lo;
        hi = pack_hl(oacc[nt][2] * i1, oacc[nt][3] * i1, lo);
        *(uint32_t*)(ctxh + ob8 + d) = hi;
        *(uint32_t*)(ctxl + ob8 + d) = lo;
    }
}

// ---------------- weight split ----------------
__global__ void wsplit_kernel(const float* __restrict__ w, bf16* __restrict__ h,
                              bf16* __restrict__ l, int n)
{
    int i = blockIdx.x * 256 + threadIdx.x;
    if (i < n) {
        bf16 hh, ll;
        split_pair(w[i], hh, ll);
        h[i] = hh; l[i] = ll;
    }
}

// ---------------- LayerNorm -> bf16 hi/lo; optional depth skip -------------
__global__ void ln_kernel(const float* __restrict__ in, const float* __restrict__ w,
                          const float* __restrict__ b, bf16* __restrict__ oh,
                          bf16* __restrict__ ol, const int* __restrict__ dsort, int level)
{
    const int row = blockIdx.x;
    if (dsort && dsort[row] < level) return;
    float4 v = ((const float4*)(in + (size_t)row * DD))[threadIdx.x];
    float s = warp_sum(v.x + v.y + v.z + v.w);
    float s2 = warp_sum(v.x * v.x + v.y * v.y + v.z * v.z + v.w * v.w);
    __shared__ float shs[8], shq[8];
    int wid = threadIdx.x >> 5, lane = threadIdx.x & 31;
    if (lane == 0) { shs[wid] = s; shq[wid] = s2; }
    __syncthreads();
    if (wid == 0) {
        float a = (lane < 8) ? shs[lane] : 0.f, c = (lane < 8) ? shq[lane] : 0.f;
        a = warp_sum(a); c = warp_sum(c);
        if (lane == 0) {
            float mu = a * (1.0f / DD);
            shs[0] = mu; shq[0] = rsqrtf(c * (1.0f / DD) - mu * mu + 1e-5f);
        }
    }
    __syncthreads();
    float mu = shs[0], rstd = shq[0];
    float4 wv = ((const float4*)w)[threadIdx.x], bv = ((const float4*)b)[threadIdx.x];
    float o0 = (v.x - mu) * rstd * wv.x + bv.x;
    float o1 = (v.y - mu) * rstd * wv.y + bv.y;
    float o2 = (v.z - mu) * rstd * wv.z + bv.z;
    float o3 = (v.w - mu) * rstd * wv.w + bv.w;
    uint32_t lo0, hi0 = pack_hl(o0, o1, lo0);
    uint32_t lo1, hi1 = pack_hl(o2, o3, lo1);
    size_t base = (size_t)row * DD + threadIdx.x * 4;
    *(uint32_t*)(oh + base) = hi0; *(uint32_t*)(oh + base + 2) = hi1;
    *(uint32_t*)(ol + base) = lo0; *(uint32_t*)(ol + base + 2) = lo1;
}

// ---------------- V transpose (skip fully-frozen tiles) ----------------
__global__ void vtrans_kernel(const bf16* __restrict__ qh, const bf16* __restrict__ ql,
                              bf16* __restrict__ vTh, bf16* __restrict__ vTl,
                              const int* __restrict__ dsort, int level)
{
    __shared__ bf16 th[64][68], tl[64][68];
    const int z = blockIdx.y, b = z >> 4, h = z & 15;
    const int l0 = blockIdx.x * 64;
    if (dsort[b * 1024 + l0] < level) return;
    const size_t base = ((size_t)b * LL + l0) * 3072 + 2048 + h * 64;
    for (int idx = threadIdx.x; idx < 64 * 64; idx += 256) {
        int li = idx >> 6, d = idx & 63;
        size_t g = base + (size_t)li * 3072 + d;
        th[li][d] = qh[g]; tl[li][d] = ql[g];
    }
    __syncthreads();
    const size_t ob = (size_t)z * (64 * LL) + l0;
    for (int idx = threadIdx.x; idx < 64 * 64; idx += 256) {
        int d = idx >> 6, li = idx & 63;
        vTh[ob + (size_t)d * LL + li] = th[li][d];
        vTl[ob + (size_t)d * LL + li] = tl[li][d];
    }
}

// ---------------- router ----------------
__global__ void router_kernel(const float* __restrict__ rh, const float* __restrict__ w2,
                              const float* __restrict__ b2, float* __restrict__ logits,
                              int* __restrict__ depths)
{
    const int row = blockIdx.x, tid = threadIdx.x;
    float part[MDD] = {0, 0, 0, 0, 0, 0};
    const float* x = rh + (size_t)row * DD;
    for (int i = tid; i < DD; i += 128) {
        float v = x[i];
        #pragma unroll
        for (int d = 0; d < MDD; d++) part[d] = fmaf(v, w2[d * DD + i], part[d]);
    }
    #pragma unroll
    for (int d = 0; d < MDD; d++) part[d] = warp_sum(part[d]);
    __shared__ float sh[MDD][4];
    int wid = tid >> 5, lane = tid & 31;
    if (lane == 0) {
        #pragma unroll
        for (int d = 0; d < MDD; d++) sh[d][wid] = part[d];
    }
    __syncthreads();
    if (tid == 0) {
        float best = -1e30f; int bi = 0;
        #pragma unroll
        for (int d = 0; d < MDD; d++) {
            float Lg = sh[d][0] + sh[d][1] + sh[d][2] + sh[d][3] + b2[d];
            logits[(size_t)row * MDD + d] = Lg;
            if (Lg > best) { best = Lg; bi = d; }
        }
        depths[row] = bi + 1;
    }
}

// ---------------- deterministic per-batch depth sort (descending) ----------
__global__ void sort_kernel(const int* __restrict__ depths, int* __restrict__ perm,
                            int* __restrict__ inv, int* __restrict__ dsort)
{
    __shared__ int sdep[1024];
    __shared__ int base[8];
    const int b = blockIdx.x, t = threadIdx.x;
    const int g = b * 1024 + t;
    const int d = depths[g];
    sdep[t] = d;
    __syncthreads();
    if (t == 0) {
        int cnt[7] = {0, 0, 0, 0, 0, 0, 0};
        for (int i = 0; i < 1024; i++) cnt[MDD - sdep[i]]++;
        int acc = 0;
        for (int k = 0; k < 6; k++) { base[k] = acc; acc += cnt[k]; }
    }
    __syncthreads();
    int rank = 0;
    for (int j = 0; j < t; j++) rank += (sdep[j] == d);
    const int pos = base[MDD - d] + rank;
    perm[b * 1024 + pos] = g;
    inv[g] = b * 1024 + pos;
    dsort[b * 1024 + pos] = d;
}

__global__ void gather_kernel(const float* __restrict__ src, const int* __restrict__ perm,
                              float* __restrict__ dst)
{
    const int row = blockIdx.x;
    const int sr = perm[row];
    ((float4*)(dst + (size_t)row * DD))[threadIdx.x] =
        ((const float4*)(src + (size_t)sr * DD))[threadIdx.x];
}

__global__ void pack_kernel(const float* __restrict__ cur, const int* __restrict__ inv,
                            const int* __restrict__ depths, const float* __restrict__ logits,
                            float* __restrict__ out, int out_size)
{
    int i = blockIdx.x * blockDim.x + threadIdx.x;
    if (i >= out_size) return;
    if (i < NCUR) {
        int r = i >> 10, c = i & 1023;
        out[i] = cur[(size_t)inv[r] * DD + c];
    } else {
        int r = i - NCUR;
        if (r < ROWS) out[i] = (float)depths[r];
        else if (r - ROWS < ROWS * MDD) out[i] = logits[r - ROWS];
        else out[i] = 0.0f;
    }
}

// ---------------------------------------------------------------------------
#define SMEM128 (2 * (20480 + 128 * 160))   // 81920
#define SMEMFL  92160

extern "C" void kernel_launch(void* const* d_in, const int* in_sizes, int n_in,
                              void* d_out, int out_size)
{
    (void)in_sizes; (void)n_in;
    const float* x           = (const float*)d_in[0];
    const float* attn_norm_w = (const float*)d_in[1];
    const float* attn_norm_b = (const float*)d_in[2];
    const float* in_proj_w   = (const float*)d_in[3];
    const float* in_proj_b   = (const float*)d_in[4];
    const float* out_proj_w  = (const float*)d_in[5];
    const float* out_proj_b  = (const float*)d_in[6];
    const float* ffn_norm_w  = (const float*)d_in[7];
    const float* ffn_norm_b  = (const float*)d_in[8];
    const float* ffn_w1      = (const float*)d_in[9];
    const float* ffn_b1      = (const float*)d_in[10];
    const float* ffn_w2      = (const float*)d_in[11];
    const float* ffn_b2      = (const float*)d_in[12];
    const float* rt_norm_w   = (const float*)d_in[13];
    const float* rt_norm_b   = (const float*)d_in[14];
    const float* rt_w1       = (const float*)d_in[15];
    const float* rt_b1       = (const float*)d_in[16];
    const float* rt_w2       = (const float*)d_in[17];
    const float* rt_b2       = (const float*)d_in[18];

    float *cur, *x2, *rh, *logits;
    int *depths, *dsort, *perm, *inv;
    bf16 *lnh, *lnl, *qkvh, *qkvl, *vTh, *vTl, *ctxh, *ctxl, *hidh, *hidl;
    bf16 *wqh, *wql, *woh, *wol, *w1h, *w1l, *w2h, *w2l, *rwh, *rwl;
    cudaGetSymbolAddress((void**)&cur, g_cur);
    cudaGetSymbolAddress((void**)&x2, g_x2);
    cudaGetSymbolAddress((void**)&rh, g_rh);
    cudaGetSymbolAddress((void**)&logits, g_logits);
    cudaGetSymbolAddress((void**)&depths, g_depths);
    cudaGetSymbolAddress((void**)&dsort, g_dsort);
    cudaGetSymbolAddress((void**)&perm, g_perm);
    cudaGetSymbolAddress((void**)&inv, g_inv);
    cudaGetSymbolAddress((void**)&lnh, g_lnh);   cudaGetSymbolAddress((void**)&lnl, g_lnl);
    cudaGetSymbolAddress((void**)&qkvh, g_qkvh); cudaGetSymbolAddress((void**)&qkvl, g_qkvl);
    cudaGetSymbolAddress((void**)&vTh, g_vTh);   cudaGetSymbolAddress((void**)&vTl, g_vTl);
    cudaGetSymbolAddress((void**)&ctxh, g_ctxh); cudaGetSymbolAddress((void**)&ctxl, g_ctxl);
    cudaGetSymbolAddress((void**)&hidh, g_hidh); cudaGetSymbolAddress((void**)&hidl, g_hidl);
    cudaGetSymbolAddress((void**)&wqh, g_wqh);   cudaGetSymbolAddress((void**)&wql, g_wql);
    cudaGetSymbolAddress((void**)&woh, g_woh);   cudaGetSymbolAddress((void**)&wol, g_wol);
    cudaGetSymbolAddress((void**)&w1h, g_w1h);   cudaGetSymbolAddress((void**)&w1l, g_w1l);
    cudaGetSymbolAddress((void**)&w2h, g_w2h);   cudaGetSymbolAddress((void**)&w2l, g_w2l);
    cudaGetSymbolAddress((void**)&rwh, g_rwh);   cudaGetSymbolAddress((void**)&rwl, g_rwl);

    cudaFuncSetAttribute(gemm_bf<2,128,0,0,0>, cudaFuncAttributeMaxDynamicSharedMemorySize, SMEM128);
    cudaFuncSetAttribute(gemm_bf<1,128,1,1,1>, cudaFuncAttributeMaxDynamicSharedMemorySize, SMEM128);
    cudaFuncSetAttribute(gemm_bf<3,128,0,1,0>, cudaFuncAttributeMaxDynamicSharedMemorySize, SMEM128);
    cudaFuncSetAttribute(gemm_bf<2,128,1,1,0>, cudaFuncAttributeMaxDynamicSharedMemorySize, SMEM128);
    cudaFuncSetAttribute(gemm_bf<4,128,0,1,0>, cudaFuncAttributeMaxDynamicSharedMemorySize, SMEM128);
    cudaFuncSetAttribute(flash_kernel,         cudaFuncAttributeMaxDynamicSharedMemorySize, SMEMFL);

    // ---- split weights once per launch ----
    wsplit_kernel<<<(3 * DD * DD) / 256, 256>>>(in_proj_w,  wqh, wql, 3 * DD * DD);
    wsplit_kernel<<<(DD * DD) / 256, 256>>>(out_proj_w, woh, wol, DD * DD);
    wsplit_kernel<<<(DFF * DD) / 256, 256>>>(ffn_w1,     w1h, w1l, DFF * DD);
    wsplit_kernel<<<(DD * DFF) / 256, 256>>>(ffn_w2,     w2h, w2l, DD * DFF);
    wsplit_kernel<<<(DD * DD) / 256, 256>>>(rt_w1,      rwh, rwl, DD * DD);

    // ---- router on ORIGINAL order ----
    ln_kernel<<<ROWS, 256>>>(x, rt_norm_w, rt_norm_b, lnh, lnl, nullptr, 0);
    gemm_bf<2,128,0,0,0><<<dim3(8, 64, 1), 128, SMEM128>>>(
        lnh, lnl, DD, 0, 0, rwh, rwl, DD, 0, 0, rt_b1, nullptr, nullptr, 0, 0,
        rh, nullptr, nullptr, DD, 0, 0, 0, 0, DD);
    router_kernel<<<ROWS, 128>>>(rh, rt_w2, rt_b2, logits, depths);

    // ---- sort tokens by depth (desc) within each batch; permute x -> cur ----
    sort_kernel<<<BB, 1024>>>(depths, perm, inv, dsort);
    gather_kernel<<<ROWS, 256>>>(x, perm, cur);

    for (int level = 1; level <= MDD; level++) {
        const int lvq = level - 1;   // frozen-state threshold for qkv path
        ln_kernel<<<ROWS, 256>>>(cur, attn_norm_w, attn_norm_b, lnh, lnl, dsort, lvq);
        // qkv: Q blocks (n0<1024) skip at `level`; K/V blocks at `level-1`
        gemm_bf<1,128,1,1,1><<<dim3(24, 64, 1), 128, SMEM128>>>(
            lnh, lnl, DD, 0, 0, wqh, wql, DD, 0, 0, in_proj_b, nullptr, dsort, level, 0,
            nullptr, qkvh, qkvl, 3 * DD, 0, 0, 0, 0, DD);
        vtrans_kernel<<<dim3(LL / 64, 128), 256>>>(qkvh, qkvl, vTh, vTl, dsort, lvq);
        flash_kernel<<<dim3(16, 128), 128, SMEMFL>>>(
            qkvh, qkvl, vTh, vTl, ctxh, ctxl, dsort, level);
        gemm_bf<3,128,0,1,0><<<dim3(8, 64, 1), 128, SMEM128>>>(
            ctxh, ctxl, DD, 0, 0, woh, wol, DD, 0, 0, out_proj_b, cur, dsort, level, 0,
            x2, nullptr, nullptr, DD, 0, 0, 0, 0, DD);
        ln_kernel<<<ROWS, 256>>>(x2, ffn_norm_w, ffn_norm_b, lnh, lnl, dsort, level);
        gemm_bf<2,128,1,1,0><<<dim3(32, 64, 1), 128, SMEM128>>>(
            lnh, lnl, DD, 0, 0, w1h, w1l, DD, 0, 0, ffn_b1, nullptr, dsort, level, 0,
            nullptr, hidh, hidl, DFF, 0, 0, 0, 0, DD);
        gemm_bf<4,128,0,1,0><<<dim3(8, 64, 1), 128, SMEM128>>>(
            hidh, hidl, DFF, 0, 0, w2h, w2l, DFF, 0, 0, ffn_b2, x2, dsort, level, 0,
            cur, nullptr, nullptr, DD, 0, 0, 0, 0, DFF);
    }

    pack_kernel<<<(out_size + 255) / 256, 256>>>(cur, inv, depths, logits,
                                                 (float*)d_out, out_size);
}

// round 14
// speedup vs baseline: 1.0764x; 1.0764x over previous
#include <cuda_runtime.h>
#include <cuda_bf16.h>
#include <math.h>
#include <stdint.h>

#define BB   8
#define LL   1024
#define DD   1024
#define DFF  4096
#define MDD  6
#define ROWS (BB * LL)
#define NCUR (ROWS * DD)

typedef __nv_bfloat16 bf16;

// ---------------- device scratch ----------------
__device__ float g_cur[NCUR];          // permuted token order
__device__ float g_x2[NCUR];
__device__ float g_rh[NCUR];
__device__ float g_logits[ROWS * MDD];
__device__ int   g_depths[ROWS];
__device__ int   g_dsort[ROWS];
__device__ int   g_perm[ROWS];
__device__ int   g_inv[ROWS];

__device__ bf16 g_lnh[NCUR],  g_lnl[NCUR];
__device__ bf16 g_qkvh[ROWS * 3 * DD], g_qkvl[ROWS * 3 * DD];
__device__ bf16 g_vTh[(size_t)128 * 64 * LL], g_vTl[(size_t)128 * 64 * LL];
__device__ bf16 g_ctxh[NCUR], g_ctxl[NCUR];
__device__ bf16 g_hidh[(size_t)ROWS * DFF], g_hidl[(size_t)ROWS * DFF];
// weight splits: one contiguous region  [wq | wo | w1 | w2 | rw]
#define WQ_OFF 0
#define WO_OFF (3 * DD * DD)
#define W1_OFF (WO_OFF + DD * DD)
#define W2_OFF (W1_OFF + DFF * DD)
#define RW_OFF (W2_OFF + DD * DFF)
#define WTOT   (RW_OFF + DD * DD)
__device__ bf16 g_wh[WTOT], g_wl[WTOT];

// ---------------- helpers ----------------
__device__ __forceinline__ uint32_t smem_u32(const void* p) {
    uint32_t a;
    asm("{ .reg .u64 t; cvta.to.shared.u64 t, %1; cvt.u32.u64 %0, t; }" : "=r"(a) : "l"(p));
    return a;
}
__device__ __forceinline__ void cp16(uint32_t dst, const void* src) {
    asm volatile("cp.async.cg.shared.global [%0], [%1], 16;" :: "r"(dst), "l"(src));
}
__device__ __forceinline__ void ldmx4(uint32_t addr, uint32_t* r) {
    asm volatile("ldmatrix.sync.aligned.m8n8.x4.shared.b16 {%0,%1,%2,%3}, [%4];"
        : "=r"(r[0]), "=r"(r[1]), "=r"(r[2]), "=r"(r[3]) : "r"(addr));
}
__device__ __forceinline__ void ldmx2(uint32_t addr, uint32_t* r) {
    asm volatile("ldmatrix.sync.aligned.m8n8.x2.shared.b16 {%0,%1}, [%2];"
        : "=r"(r[0]), "=r"(r[1]) : "r"(addr));
}
__device__ __forceinline__ void mma_bf16(float* c, const uint32_t* a, const uint32_t* b) {
    asm volatile("mma.sync.aligned.m16n8k16.row.col.f32.bf16.bf16.f32 "
        "{%0,%1,%2,%3}, {%4,%5,%6,%7}, {%8,%9}, {%0,%1,%2,%3};"
        : "+f"(c[0]), "+f"(c[1]), "+f"(c[2]), "+f"(c[3])
        : "r"(a[0]), "r"(a[1]), "r"(a[2]), "r"(a[3]), "r"(b[0]), "r"(b[1]));
}
__device__ __forceinline__ void split_pair(float v, bf16& h, bf16& l) {
    h = __float2bfloat16_rn(v);
    l = __float2bfloat16_rn(v - __bfloat162float(h));
}
__device__ __forceinline__ uint32_t pack_hl(float x, float y, uint32_t& lo) {
    __nv_bfloat162 hv = __floats2bfloat162_rn(x, y);
    float2 f = __bfloat1622float2(hv);
    __nv_bfloat162 lv = __floats2bfloat162_rn(x - f.x, y - f.y);
    lo = *(uint32_t*)&lv;
    return *(uint32_t*)&hv;
}
__device__ __forceinline__ float gelu_erf(float x) {
    return 0.5f * x * (1.0f + erff(x * 0.70710678118654752440f));
}
__device__ __forceinline__ float warp_sum(float v) {
    #pragma unroll
    for (int o = 16; o > 0; o >>= 1) v += __shfl_xor_sync(0xffffffffu, v, o);
    return v;
}
__device__ __forceinline__ float warp_max(float v) {
    #pragma unroll
    for (int o = 16; o > 0; o >>= 1) v = fmaxf(v, __shfl_xor_sync(0xffffffffu, v, o));
    return v;
}

// ---------------------------------------------------------------------------
// Dense split-bf16 NT GEMM — Round-12 validated configuration (exact):
// CTA 128x{128}, 128 threads (4 warps), warp tile 64x64, 2-stage cp.async with
// early ISSUE (prefetch lead = full compute chunk), 2 CTAs/SM.
// ---------------------------------------------------------------------------
template<int MT>
__device__ __forceinline__ void compute_chunk64(uint32_t stg, uint32_t wloffB,
                                                int warp_m, int warp_n,
                                                int lane, float* acc)
{
    const uint32_t aA = stg + (warp_m * (MT * 16) + (lane & 15)) * 80 + ((lane >> 4) & 1) * 16;
    const uint32_t aB = stg + 20480
        + (warp_n * 64 + (lane & 7) + ((lane >> 4) & 1) * 8) * 80 + ((lane >> 3) & 1) * 16;
    #pragma unroll
    for (int ks = 0; ks < 2; ks++) {
        const uint32_t kso = ks * 32;
        uint32_t bh[8][2], bl[8][2];
        #pragma unroll
        for (int ntp = 0; ntp < 4; ntp++) {
            uint32_t t4[4];
            ldmx4(aB + ntp * 1280 + kso, t4);
            bh[2 * ntp][0] = t4[0]; bh[2 * ntp][1] = t4[1];
            bh[2 * ntp + 1][0] = t4[2]; bh[2 * ntp + 1][1] = t4[3];
            ldmx4(aB + wloffB + ntp * 1280 + kso, t4);
            bl[2 * ntp][0] = t4[0]; bl[2 * ntp][1] = t4[1];
            bl[2 * ntp + 1][0] = t4[2]; bl[2 * ntp + 1][1] = t4[3];
        }
        #pragma unroll
        for (int mt = 0; mt < MT; mt++) {
            uint32_t ah[4], al[4];
            ldmx4(aA + mt * 1280 + kso, ah);
            ldmx4(aA + 10240 + mt * 1280 + kso, al);
            #pragma unroll
            for (int nt = 0; nt < 8; nt++) {
                float* c = acc + (mt * 8 + nt) * 4;
                mma_bf16(c, ah, bh[nt]);
                mma_bf16(c, ah, bl[nt]);
                mma_bf16(c, al, bh[nt]);
            }
        }
    }
}

template<int EPI, int NTILE, int OUTP, int DSKIP, int QSPLIT>
__global__ void __launch_bounds__(128)
gemm_bf(const bf16* __restrict__ Ah, const bf16* __restrict__ Al, int lda, long saz, long sah,
        const bf16* __restrict__ Wh, const bf16* __restrict__ Wl, int ldw, long swz, long swh,
        const float* __restrict__ bias, const float* __restrict__ res,
        const int* __restrict__ depths, int level, long sdz,
        float* __restrict__ Cf, bf16* __restrict__ Ch, bf16* __restrict__ Cl,
        int ldc, long scz, long sch, int hsh, int hmk, int K)
{
    extern __shared__ __align__(16) char smem[];
    constexpr int WN  = NTILE / 64;
    constexpr int MT  = (WN == 2) ? 4 : 2;
    constexpr int STG = 20480 + NTILE * 160;
    const int tid = threadIdx.x, lane = tid & 31, wid = tid >> 5;
    const int warp_m = wid / WN, warp_n = wid % WN;
    const int z = blockIdx.z, zh = z >> hsh, zl = z & hmk;
    const int m0 = blockIdx.y << 7, n0 = blockIdx.x * NTILE;
    if (DSKIP) {
        int thr = (QSPLIT && n0 >= DD) ? level - 1 : level;
        if (depths[(size_t)zh * sdz + m0] < thr) return;
    }
    const size_t aoff = (size_t)zh * saz + (size_t)zl * sah + (size_t)m0 * lda;
    const size_t woff = (size_t)zh * swz + (size_t)zl * swh + (size_t)n0 * ldw;
    const bf16* Azh = Ah + aoff;
    const bf16* Azl = Al + aoff;
    const bf16* Wzh = Wh + woff;
    const bf16* Wzl = Wl + woff;
    const uint32_t sb = smem_u32(smem);

    float acc[MT * 8 * 4];
    #pragma unroll
    for (int i = 0; i < MT * 8 * 4; i++) acc[i] = 0.0f;

    const int rr0 = tid >> 2, gg = tid & 3;
    const int nchunk = K >> 5;

    #define ISSUE(cc) do { \
        uint32_t st = sb + ((cc) & 1) * STG; \
        const size_t ko = (size_t)((cc) << 5); \
        _Pragma("unroll") \
        for (int i = 0; i < 4; i++) { \
            int r = rr0 + i * 32; \
            cp16(st + r * 80 + gg * 16,         Azh + (size_t)r * lda + ko + gg * 8); \
            cp16(st + 10240 + r * 80 + gg * 16, Azl + (size_t)r * lda + ko + gg * 8); \
        } \
        _Pragma("unroll") \
        for (int i = 0; i < NTILE / 32; i++) { \
            int r = rr0 + i * 32; \
            cp16(st + 20480 + r * 80 + gg * 16,              Wzh + (size_t)r * ldw + ko + gg * 8); \
            cp16(st + 20480 + NTILE * 80 + r * 80 + gg * 16, Wzl + (size_t)r * ldw + ko + gg * 8); \
        } \
        asm volatile("cp.async.commit_group;" ::: "memory"); \
    } while (0)

    ISSUE(0);
    for (int c = 0; c < nchunk; c++) {
        if (c + 1 < nchunk) {
            ISSUE(c + 1);
            asm volatile("cp.async.wait_group 1;" ::: "memory");
        } else {
            asm volatile("cp.async.wait_group 0;" ::: "memory");
        }
        __syncthreads();
        compute_chunk64<MT>(sb + (c & 1) * STG, (uint32_t)(NTILE * 80),
                            warp_m, warp_n, lane, acc);
        __syncthreads();
    }
    #undef ISSUE

    const size_t coff = (size_t)zh * scz + (size_t)zl * sch;
    #pragma unroll
    for (int mt = 0; mt < MT; mt++) {
        #pragma unroll
        for (int h2 = 0; h2 < 2; h2++) {
            const int m = m0 + warp_m * (MT * 16) + mt * 16 + (lane >> 2) + h2 * 8;
            if (EPI == 4) { if (depths[m] < level) continue; }
            const float* Rrow = (EPI >= 3) ? (res + (size_t)m * ldc) : (const float*)0;
            #pragma unroll
            for (int nt = 0; nt < 8; nt++) {
                const int col = n0 + warp_n * 64 + nt * 8 + ((lane & 3) << 1);
                float vx = acc[(mt * 8 + nt) * 4 + h2 * 2 + 0];
                float vy = acc[(mt * 8 + nt) * 4 + h2 * 2 + 1];
                if (EPI >= 1) { vx += bias[col]; vy += bias[col + 1]; }
                if (EPI == 2) { vx = gelu_erf(vx); vy = gelu_erf(vy); }
                if (EPI >= 3) { vx += Rrow[col]; vy += Rrow[col + 1]; }
                if (OUTP == 0) {
                    *(float2*)(Cf + coff + (size_t)m * ldc + col) = make_float2(vx, vy);
                } else {
                    uint32_t lo, hi = pack_hl(vx, vy, lo);
                    *(uint32_t*)(Ch + coff + (size_t)m * ldc + col) = hi;
                    *(uint32_t*)(Cl + coff + (size_t)m * ldc + col) = lo;
                }
            }
        }
    }
}

// ---------------------------------------------------------------------------
// Flash-fused attention (Round-10/12 validated, exact).
// ---------------------------------------------------------------------------
__global__ void __launch_bounds__(128)
flash_kernel(const bf16* __restrict__ qkvh, const bf16* __restrict__ qkvl,
             const bf16* __restrict__ vTh, const bf16* __restrict__ vTl,
             bf16* __restrict__ ctxh, bf16* __restrict__ ctxl,
             const int* __restrict__ dsort, int level)
{
    extern __shared__ __align__(16) char smem[];
    const int z = blockIdx.y, b = z >> 4, h = z & 15;
    const int qb = blockIdx.x;
    if (dsort[b * 1024 + qb * 64] < level) return;
    const int tid = threadIdx.x, lane = tid & 31, wq = tid >> 5;
    const uint32_t sb = smem_u32(smem);

    const size_t qbase = ((size_t)b * 1024 + (size_t)qb * 64) * 3072 + h * 64;
    const size_t kbase = (size_t)b * 1024 * 3072 + 1024 + h * 64;
    const size_t vbase = (size_t)z * 65536;

    #pragma unroll
    for (int i = 0; i < 4; i++) {
        int idx = tid + i * 128, row = idx >> 3, g = idx & 7;
        cp16(sb + row * 144 + g * 16,        qkvh + qbase + (size_t)row * 3072 + g * 8);
        cp16(sb + 9216 + row * 144 + g * 16, qkvl + qbase + (size_t)row * 3072 + g * 8);
    }
    asm volatile("cp.async.commit_group;" ::: "memory");

    #define KV_ISSUE(kb) do { \
        uint32_t st = ((kb) & 1) * 18432; \
        _Pragma("unroll") \
        for (int i = 0; i < 4; i++) { \
            int idx = tid + i * 128, row = idx >> 3, g = idx & 7; \
            size_t ks = kbase + ((size_t)((kb) * 64 + row)) * 3072 + g * 8; \
            cp16(sb + 18432 + st + row * 144 + g * 16,        qkvh + ks); \
            cp16(sb + 18432 + st + 9216 + row * 144 + g * 16, qkvl + ks); \
            size_t vs = vbase + (size_t)row * 1024 + (kb) * 64 + g * 8; \
            cp16(sb + 55296 + st + row * 144 + g * 16,        vTh + vs); \
            cp16(sb + 55296 + st + 9216 + row * 144 + g * 16, vTl + vs); \
        } \
        asm volatile("cp.async.commit_group;" ::: "memory"); \
    } while (0)

    KV_ISSUE(0);

    uint32_t qh_[4][4], ql_[4][4];
    float oacc[8][4];
    #pragma unroll
    for (int nt = 0; nt < 8; nt++)
        #pragma unroll
        for (int j = 0; j < 4; j++) oacc[nt][j] = 0.0f;
    float m0 = -1e30f, m1 = -1e30f, l0 = 0.0f, l1 = 0.0f;

    const uint32_t qa = sb + (wq * 16 + (lane & 15)) * 144 + ((lane >> 4) & 1) * 16;
    const uint32_t bofs = (lane & 7) * 144 + ((lane >> 3) & 1) * 16;

    for (int kb = 0; kb < 16; kb++) {
        if (kb + 1 < 16) {
            KV_ISSUE(kb + 1);
            asm volatile("cp.async.wait_group 1;" ::: "memory");
        } else {
            asm volatile("cp.async.wait_group 0;" ::: "memory");
        }
        __syncthreads();
        if (kb == 0) {
            #pragma unroll
            for (int kc = 0; kc < 4; kc++) {
                ldmx4(qa + kc * 32, qh_[kc]);
                ldmx4(qa + 9216 + kc * 32, ql_[kc]);
            }
        }
        const uint32_t kt = sb + 18432 + (kb & 1) * 18432 + bofs;
        float s[8][4];
        #pragma unroll
        for (int nt = 0; nt < 8; nt++)
            #pragma unroll
            for (int j = 0; j < 4; j++) s[nt][j] = 0.0f;
        #pragma unroll
        for (int kc = 0; kc < 4; kc++) {
            uint32_t bh[8][2], bl[8][2];
            #pragma unroll
            for (int nt = 0; nt < 8; nt++) {
                ldmx2(kt + nt * 1152 + kc * 32, bh[nt]);
                ldmx2(kt + 9216 + nt * 1152 + kc * 32, bl[nt]);
            }
            #pragma unroll
            for (int nt = 0; nt < 8; nt++) {
                mma_bf16(s[nt], qh_[kc], bh[nt]);
                mma_bf16(s[nt], qh_[kc], bl[nt]);
                mma_bf16(s[nt], ql_[kc], bh[nt]);
            }
        }
        float mx0 = -1e30f, mx1 = -1e30f;
        #pragma unroll
        for (int nt = 0; nt < 8; nt++) {
            mx0 = fmaxf(mx0, fmaxf(s[nt][0], s[nt][1]));
            mx1 = fmaxf(mx1, fmaxf(s[nt][2], s[nt][3]));
        }
        mx0 = fmaxf(mx0, __shfl_xor_sync(0xffffffffu, mx0, 1));
        mx0 = fmaxf(mx0, __shfl_xor_sync(0xffffffffu, mx0, 2));
        mx1 = fmaxf(mx1, __shfl_xor_sync(0xffffffffu, mx1, 1));
        mx1 = fmaxf(mx1, __shfl_xor_sync(0xffffffffu, mx1, 2));
        const float nm0 = fmaxf(m0, mx0 * 0.125f);
        const float nm1 = fmaxf(m1, mx1 * 0.125f);
        const float a0 = __expf(m0 - nm0);
        const float a1 = __expf(m1 - nm1);
        float rs0 = 0.0f, rs1 = 0.0f;
        #pragma unroll
        for (int nt = 0; nt < 8; nt++) {
            s[nt][0] = __expf(s[nt][0] * 0.125f - nm0);
            s[nt][1] = __expf(s[nt][1] * 0.125f - nm0);
            s[nt][2] = __expf(s[nt][2] * 0.125f - nm1);
            s[nt][3] = __expf(s[nt][3] * 0.125f - nm1);
            rs0 += s[nt][0] + s[nt][1];
            rs1 += s[nt][2] + s[nt][3];
        }
        rs0 += __shfl_xor_sync(0xffffffffu, rs0, 1);
        rs0 += __shfl_xor_sync(0xffffffffu, rs0, 2);
        rs1 += __shfl_xor_sync(0xffffffffu, rs1, 1);
        rs1 += __shfl_xor_sync(0xffffffffu, rs1, 2);
        l0 = a0 * l0 + rs0;
        l1 = a1 * l1 + rs1;
        m0 = nm0; m1 = nm1;
        #pragma unroll
        for (int nt = 0; nt < 8; nt++) {
            oacc[nt][0] *= a0; oacc[nt][1] *= a0;
            oacc[nt][2] *= a1; oacc[nt][3] *= a1;
        }
        const uint32_t vt = sb + 55296 + (kb & 1) * 18432 + bofs;
        #pragma unroll
        for (int kc = 0; kc < 4; kc++) {
            uint32_t pah[4], pal[4];
            pah[0] = pack_hl(s[2 * kc][0],     s[2 * kc][1],     pal[0]);
            pah[1] = pack_hl(s[2 * kc][2],     s[2 * kc][3],     pal[1]);
            pah[2] = pack_hl(s[2 * kc + 1][0], s[2 * kc + 1][1], pal[2]);
            pah[3] = pack_hl(s[2 * kc + 1][2], s[2 * kc + 1][3], pal[3]);
            uint32_t vbh[8][2], vbl[8][2];
            #pragma unroll
            for (int nt = 0; nt < 8; nt++) {
                ldmx2(vt + nt * 1152 + kc * 32, vbh[nt]);
                ldmx2(vt + 9216 + nt * 1152 + kc * 32, vbl[nt]);
            }
            #pragma unroll
            for (int nt = 0; nt < 8; nt++) {
                mma_bf16(oacc[nt], pah, vbh[nt]);
                mma_bf16(oacc[nt], pah, vbl[nt]);
                mma_bf16(oacc[nt], pal, vbh[nt]);
            }
        }
        __syncthreads();
    }
    #undef KV_ISSUE

    const float i0 = 1.0f / l0, i1 = 1.0f / l1;
    const int token = b * 1024 + qb * 64 + wq * 16 + (lane >> 2);
    const size_t ob  = (size_t)token * 1024 + h * 64;
    const size_t ob8 = ob + 8 * 1024;
    #pragma unroll
    for (int nt = 0; nt < 8; nt++) {
        const int d = nt * 8 + ((lane & 3) << 1);
        uint32_t lo, hi;
        hi = pack_hl(oacc[nt][0] * i0, oacc[nt][1] * i0, lo);
        *(uint32_t*)(ctxh + ob + d) = hi;
        *(uint32_t*)(ctxl + ob + d) = lo;
        hi = pack_hl(oacc[nt][2] * i1, oacc[nt][3] * i1, lo);
        *(uint32_t*)(ctxh + ob8 + d) = hi;
        *(uint32_t*)(ctxl + ob8 + d) = lo;
    }
}

// ---------------- weight split: all weights in ONE launch -------------------
__global__ void wsplit_all_kernel(const float* __restrict__ wq, const float* __restrict__ wo,
                                  const float* __restrict__ w1, const float* __restrict__ w2,
                                  const float* __restrict__ rw,
                                  bf16* __restrict__ h, bf16* __restrict__ l)
{
    int i = blockIdx.x * 256 + threadIdx.x;
    if (i >= WTOT) return;
    float v;
    if (i < WO_OFF)      v = wq[i];
    else if (i < W1_OFF) v = wo[i - WO_OFF];
    else if (i < W2_OFF) v = w1[i - W1_OFF];
    else if (i < RW_OFF) v = w2[i - W2_OFF];
    else                 v = rw[i - RW_OFF];
    bf16 hh, ll;
    split_pair(v, hh, ll);
    h[i] = hh; l[i] = ll;
}

// ---------------- LayerNorm -> bf16 hi/lo; optional depth skip -------------
__global__ void ln_kernel(const float* __restrict__ in, const float* __restrict__ w,
                          const float* __restrict__ b, bf16* __restrict__ oh,
                          bf16* __restrict__ ol, const int* __restrict__ dsort, int level)
{
    const int row = blockIdx.x;
    if (dsort && dsort[row] < level) return;
    float4 v = ((const float4*)(in + (size_t)row * DD))[threadIdx.x];
    float s = warp_sum(v.x + v.y + v.z + v.w);
    float s2 = warp_sum(v.x * v.x + v.y * v.y + v.z * v.z + v.w * v.w);
    __shared__ float shs[8], shq[8];
    int wid = threadIdx.x >> 5, lane = threadIdx.x & 31;
    if (lane == 0) { shs[wid] = s; shq[wid] = s2; }
    __syncthreads();
    if (wid == 0) {
        float a = (lane < 8) ? shs[lane] : 0.f, c = (lane < 8) ? shq[lane] : 0.f;
        a = warp_sum(a); c = warp_sum(c);
        if (lane == 0) {
            float mu = a * (1.0f / DD);
            shs[0] = mu; shq[0] = rsqrtf(c * (1.0f / DD) - mu * mu + 1e-5f);
        }
    }
    __syncthreads();
    float mu = shs[0], rstd = shq[0];
    float4 wv = ((const float4*)w)[threadIdx.x], bv = ((const float4*)b)[threadIdx.x];
    float o0 = (v.x - mu) * rstd * wv.x + bv.x;
    float o1 = (v.y - mu) * rstd * wv.y + bv.y;
    float o2 = (v.z - mu) * rstd * wv.z + bv.z;
    float o3 = (v.w - mu) * rstd * wv.w + bv.w;
    uint32_t lo0, hi0 = pack_hl(o0, o1, lo0);
    uint32_t lo1, hi1 = pack_hl(o2, o3, lo1);
    size_t base = (size_t)row * DD + threadIdx.x * 4;
    *(uint32_t*)(oh + base) = hi0; *(uint32_t*)(oh + base + 2) = hi1;
    *(uint32_t*)(ol + base) = lo0; *(uint32_t*)(ol + base + 2) = lo1;
}

// ---------------- V transpose (skip fully-frozen tiles) ----------------
__global__ void vtrans_kernel(const bf16* __restrict__ qh, const bf16* __restrict__ ql,
                              bf16* __restrict__ vTh, bf16* __restrict__ vTl,
                              const int* __restrict__ dsort, int level)
{
    __shared__ bf16 th[64][68], tl[64][68];
    const int z = blockIdx.y, b = z >> 4, h = z & 15;
    const int l0 = blockIdx.x * 64;
    if (dsort[b * 1024 + l0] < level) return;
    const size_t base = ((size_t)b * LL + l0) * 3072 + 2048 + h * 64;
    for (int idx = threadIdx.x; idx < 64 * 64; idx += 256) {
        int li = idx >> 6, d = idx & 63;
        size_t g = base + (size_t)li * 3072 + d;
        th[li][d] = qh[g]; tl[li][d] = ql[g];
    }
    __syncthreads();
    const size_t ob = (size_t)z * (64 * LL) + l0;
    for (int idx = threadIdx.x; idx < 64 * 64; idx += 256) {
        int d = idx >> 6, li = idx & 63;
        vTh[ob + (size_t)d * LL + li] = th[li][d];
        vTl[ob + (size_t)d * LL + li] = tl[li][d];
    }
}

// ---------------- router ----------------
__global__ void router_kernel(const float* __restrict__ rh, const float* __restrict__ w2,
                              const float* __restrict__ b2, float* __restrict__ logits,
                              int* __restrict__ depths)
{
    const int row = blockIdx.x, tid = threadIdx.x;
    float part[MDD] = {0, 0, 0, 0, 0, 0};
    const float* x = rh + (size_t)row * DD;
    for (int i = tid; i < DD; i += 128) {
        float v = x[i];
        #pragma unroll
        for (int d = 0; d < MDD; d++) part[d] = fmaf(v, w2[d * DD + i], part[d]);
    }
    #pragma unroll
    for (int d = 0; d < MDD; d++) part[d] = warp_sum(part[d]);
    __shared__ float sh[MDD][4];
    int wid = tid >> 5, lane = tid & 31;
    if (lane == 0) {
        #pragma unroll
        for (int d = 0; d < MDD; d++) sh[d][wid] = part[d];
    }
    __syncthreads();
    if (tid == 0) {
        float best = -1e30f; int bi = 0;
        #pragma unroll
        for (int d = 0; d < MDD; d++) {
            float Lg = sh[d][0] + sh[d][1] + sh[d][2] + sh[d][3] + b2[d];
            logits[(size_t)row * MDD + d] = Lg;
            if (Lg > best) { best = Lg; bi = d; }
        }
        depths[row] = bi + 1;
    }
}

// ---------------- deterministic per-batch depth sort (descending) ----------
__global__ void sort_kernel(const int* __restrict__ depths, int* __restrict__ perm,
                            int* __restrict__ inv, int* __restrict__ dsort)
{
    __shared__ int sdep[1024];
    __shared__ int base[8];
    const int b = blockIdx.x, t = threadIdx.x;
    const int g = b * 1024 + t;
    const int d = depths[g];
    sdep[t] = d;
    __syncthreads();
    if (t == 0) {
        int cnt[7] = {0, 0, 0, 0, 0, 0, 0};
        for (int i = 0; i < 1024; i++) cnt[MDD - sdep[i]]++;
        int acc = 0;
        for (int k = 0; k < 6; k++) { base[k] = acc; acc += cnt[k]; }
    }
    __syncthreads();
    int rank = 0;
    for (int j = 0; j < t; j++) rank += (sdep[j] == d);
    const int pos = base[MDD - d] + rank;
    perm[b * 1024 + pos] = g;
    inv[g] = b * 1024 + pos;
    dsort[b * 1024 + pos] = d;
}

__global__ void gather_kernel(const float* __restrict__ src, const int* __restrict__ perm,
                              float* __restrict__ dst)
{
    const int row = blockIdx.x;
    const int sr = perm[row];
    ((float4*)(dst + (size_t)row * DD))[threadIdx.x] =
        ((const float4*)(src + (size_t)sr * DD))[threadIdx.x];
}

__global__ void pack_kernel(const float* __restrict__ cur, const int* __restrict__ inv,
                            const int* __restrict__ depths, const float* __restrict__ logits,
                            float* __restrict__ out, int out_size)
{
    int i = blockIdx.x * blockDim.x + threadIdx.x;
    if (i >= out_size) return;
    if (i < NCUR) {
        int r = i >> 10, c = i & 1023;
        out[i] = cur[(size_t)inv[r] * DD + c];
    } else {
        int r = i - NCUR;
        if (r < ROWS) out[i] = (float)depths[r];
        else if (r - ROWS < ROWS * MDD) out[i] = logits[r - ROWS];
        else out[i] = 0.0f;
    }
}

// ---------------------------------------------------------------------------
#define SMEM128 (2 * (20480 + 128 * 160))   // 81920
#define SMEMFL  92160

extern "C" void kernel_launch(void* const* d_in, const int* in_sizes, int n_in,
                              void* d_out, int out_size)
{
    (void)in_sizes; (void)n_in;
    const float* x           = (const float*)d_in[0];
    const float* attn_norm_w = (const float*)d_in[1];
    const float* attn_norm_b = (const float*)d_in[2];
    const float* in_proj_w   = (const float*)d_in[3];
    const float* in_proj_b   = (const float*)d_in[4];
    const float* out_proj_w  = (const float*)d_in[5];
    const float* out_proj_b  = (const float*)d_in[6];
    const float* ffn_norm_w  = (const float*)d_in[7];
    const float* ffn_norm_b  = (const float*)d_in[8];
    const float* ffn_w1      = (const float*)d_in[9];
    const float* ffn_b1      = (const float*)d_in[10];
    const float* ffn_w2      = (const float*)d_in[11];
    const float* ffn_b2      = (const float*)d_in[12];
    const float* rt_norm_w   = (const float*)d_in[13];
    const float* rt_norm_b   = (const float*)d_in[14];
    const float* rt_w1       = (const float*)d_in[15];
    const float* rt_b1       = (const float*)d_in[16];
    const float* rt_w2       = (const float*)d_in[17];
    const float* rt_b2       = (const float*)d_in[18];

    float *cur, *x2, *rh, *logits;
    int *depths, *dsort, *perm, *inv;
    bf16 *lnh, *lnl, *qkvh, *qkvl, *vTh, *vTl, *ctxh, *ctxl, *hidh, *hidl;
    bf16 *wh, *wl;
    cudaGetSymbolAddress((void**)&cur, g_cur);
    cudaGetSymbolAddress((void**)&x2, g_x2);
    cudaGetSymbolAddress((void**)&rh, g_rh);
    cudaGetSymbolAddress((void**)&logits, g_logits);
    cudaGetSymbolAddress((void**)&depths, g_depths);
    cudaGetSymbolAddress((void**)&dsort, g_dsort);
    cudaGetSymbolAddress((void**)&perm, g_perm);
    cudaGetSymbolAddress((void**)&inv, g_inv);
    cudaGetSymbolAddress((void**)&lnh, g_lnh);   cudaGetSymbolAddress((void**)&lnl, g_lnl);
    cudaGetSymbolAddress((void**)&qkvh, g_qkvh); cudaGetSymbolAddress((void**)&qkvl, g_qkvl);
    cudaGetSymbolAddress((void**)&vTh, g_vTh);   cudaGetSymbolAddress((void**)&vTl, g_vTl);
    cudaGetSymbolAddress((void**)&ctxh, g_ctxh); cudaGetSymbolAddress((void**)&ctxl, g_ctxl);
    cudaGetSymbolAddress((void**)&hidh, g_hidh); cudaGetSymbolAddress((void**)&hidl, g_hidl);
    cudaGetSymbolAddress((void**)&wh, g_wh);     cudaGetSymbolAddress((void**)&wl, g_wl);

    bf16 *wqh = wh + WQ_OFF, *wql = wl + WQ_OFF;
    bf16 *woh = wh + WO_OFF, *wol = wl + WO_OFF;
    bf16 *w1h = wh + W1_OFF, *w1l = wl + W1_OFF;
    bf16 *w2h = wh + W2_OFF, *w2l = wl + W2_OFF;
    bf16 *rwh = wh + RW_OFF, *rwl = wl + RW_OFF;

    cudaFuncSetAttribute(gemm_bf<2,128,0,0,0>, cudaFuncAttributeMaxDynamicSharedMemorySize, SMEM128);
    cudaFuncSetAttribute(gemm_bf<1,128,1,1,1>, cudaFuncAttributeMaxDynamicSharedMemorySize, SMEM128);
    cudaFuncSetAttribute(gemm_bf<3,128,0,1,0>, cudaFuncAttributeMaxDynamicSharedMemorySize, SMEM128);
    cudaFuncSetAttribute(gemm_bf<2,128,1,1,0>, cudaFuncAttributeMaxDynamicSharedMemorySize, SMEM128);
    cudaFuncSetAttribute(gemm_bf<4,128,0,1,0>, cudaFuncAttributeMaxDynamicSharedMemorySize, SMEM128);
    cudaFuncSetAttribute(flash_kernel,         cudaFuncAttributeMaxDynamicSharedMemorySize, SMEMFL);

    // ---- split ALL weights in one launch ----
    wsplit_all_kernel<<<(WTOT + 255) / 256, 256>>>(in_proj_w, out_proj_w, ffn_w1,
                                                   ffn_w2, rt_w1, wh, wl);

    // ---- router on ORIGINAL order ----
    ln_kernel<<<ROWS, 256>>>(x, rt_norm_w, rt_norm_b, lnh, lnl, nullptr, 0);
    gemm_bf<2,128,0,0,0><<<dim3(8, 64, 1), 128, SMEM128>>>(
        lnh, lnl, DD, 0, 0, rwh, rwl, DD, 0, 0, rt_b1, nullptr, nullptr, 0, 0,
        rh, nullptr, nullptr, DD, 0, 0, 0, 0, DD);
    router_kernel<<<ROWS, 128>>>(rh, rt_w2, rt_b2, logits, depths);

    // ---- sort tokens by depth (desc) within each batch; permute x -> cur ----
    sort_kernel<<<BB, 1024>>>(depths, perm, inv, dsort);
    gather_kernel<<<ROWS, 256>>>(x, perm, cur);

    for (int level = 1; level <= MDD; level++) {
        const int lvq = level - 1;   // frozen-state threshold for qkv path
        ln_kernel<<<ROWS, 256>>>(cur, attn_norm_w, attn_norm_b, lnh, lnl, dsort, lvq);
        // qkv: Q blocks (n0<1024) skip at `level`; K/V blocks at `level-1`
        gemm_bf<1,128,1,1,1><<<dim3(24, 64, 1), 128, SMEM128>>>(
            lnh, lnl, DD, 0, 0, wqh, wql, DD, 0, 0, in_proj_b, nullptr, dsort, level, 0,
            nullptr, qkvh, qkvl, 3 * DD, 0, 0, 0, 0, DD);
        vtrans_kernel<<<dim3(LL / 64, 128), 256>>>(qkvh, qkvl, vTh, vTl, dsort, lvq);
        flash_kernel<<<dim3(16, 128), 128, SMEMFL>>>(
            qkvh, qkvl, vTh, vTl, ctxh, ctxl, dsort, level);
        gemm_bf<3,128,0,1,0><<<dim3(8, 64, 1), 128, SMEM128>>>(
            ctxh, ctxl, DD, 0, 0, woh, wol, DD, 0, 0, out_proj_b, cur, dsort, level, 0,
            x2, nullptr, nullptr, DD, 0, 0, 0, 0, DD);
        ln_kernel<<<ROWS, 256>>>(x2, ffn_norm_w, ffn_norm_b, lnh, lnl, dsort, level);
        gemm_bf<2,128,1,1,0><<<dim3(32, 64, 1), 128, SMEM128>>>(
            lnh, lnl, DD, 0, 0, w1h, w1l, DD, 0, 0, ffn_b1, nullptr, dsort, level, 0,
            nullptr, hidh, hidl, DFF, 0, 0, 0, 0, DD);
        gemm_bf<4,128,0,1,0><<<dim3(8, 64, 1), 128, SMEM128>>>(
            hidh, hidl, DFF, 0, 0, w2h, w2l, DFF, 0, 0, ffn_b2, x2, dsort, level, 0,
            cur, nullptr, nullptr, DD, 0, 0, 0, 0, DFF);
    }

    pack_kernel<<<(out_size + 255) / 256, 256>>>(cur, inv, depths, logits,
                                                 (float*)d_out, out_size);
}